// round 10
// baseline (speedup 1.0000x reference)
#include <cuda_runtime.h>
#include <cuda_bf16.h>
#include <math.h>
#include <cstdint>

#define SEQ     8192
#define BATCH   4
#define DREC    1024
#define NCHUNK  128
#define CHUNKSZ 64
#define MROWS   (BATCH * SEQ)      // 32768
#define KDIM    1024

#if defined(__CUDA_ARCH_FEAT_SM103_ALL) || defined(__CUDA_ARCH_FEAT_SM100_ALL) || defined(__CUDA_ARCH_FEAT_SM101_ALL)
#define TC_OK 1
#else
#define TC_OK 0
#endif

// ---------------- scratch ----------------
__device__ float g_aiv[(size_t)MROWS * 3 * DREC];
__device__ float g_ctd[BATCH * NCHUNK * DREC];
__device__ float g_cfs[BATCH * NCHUNK * DREC];
__device__ float g_inc[BATCH * NCHUNK * DREC];
__device__ __nv_bfloat16 g_xh[(size_t)MROWS * KDIM];
__device__ __nv_bfloat16 g_xl[(size_t)MROWS * KDIM];
__device__ __nv_bfloat16 g_hh[(size_t)MROWS * DREC];
__device__ __nv_bfloat16 g_hl[(size_t)MROWS * DREC];
__device__ __nv_bfloat16 g_w1th[3072 * 1024];
__device__ __nv_bfloat16 g_w1tl[3072 * 1024];
__device__ __nv_bfloat16 g_w2th[1024 * 1024];
__device__ __nv_bfloat16 g_w2tl[1024 * 1024];

// ---------------- PTX helpers ----------------
__device__ __forceinline__ uint32_t smem_to_u32(const void* p) {
    uint32_t a;
    asm("{ .reg .u64 t; cvta.to.shared.u64 t, %1; cvt.u32.u64 %0, t; }" : "=r"(a) : "l"(p));
    return a;
}
__device__ __forceinline__ uint32_t elect_one_pred() {
    uint32_t p;
    asm volatile("{\n\t.reg .pred p;\n\telect.sync _|p, 0xFFFFFFFF;\n\tselp.b32 %0, 1, 0, p;\n\t}" : "=r"(p));
    return p;
}
#define MBARRIER_INIT(addr, cnt) \
    asm volatile("mbarrier.init.shared.b64 [%0], %1;" :: "r"((uint32_t)(addr)), "r"((uint32_t)(cnt)) : "memory")
#define MBARRIER_INVAL(addr) \
    asm volatile("mbarrier.inval.shared.b64 [%0];" :: "r"((uint32_t)(addr)) : "memory")
#define MBARRIER_WAIT_PARITY(mbar_smem_addr, phase_parity) do { \
    uint32_t _mbar = (uint32_t)(mbar_smem_addr); \
    uint32_t _parity = (uint32_t)(phase_parity); \
    uint32_t _done; \
    asm volatile("{\n\t.reg .pred p;\n\t" \
        "mbarrier.try_wait.parity.acquire.cta.shared::cta.b64 p, [%1], %2;\n\t" \
        "selp.b32 %0, 1, 0, p;\n\t}" \
        : "=r"(_done) : "r"(_mbar), "r"(_parity) : "memory"); \
    if (!_done) { \
        asm volatile("{\n\t.reg .pred P1;\n\t" \
            "WAIT_LOOP_%=:\n\t" \
            "mbarrier.try_wait.parity.acquire.cta.shared::cta.b64 P1, [%0], %1, 0x989680;\n\t" \
            "@P1 bra.uni WAIT_DONE_%=;\n\t" \
            "bra.uni WAIT_LOOP_%=;\n\t" \
            "WAIT_DONE_%=:\n\t}" \
            :: "r"(_mbar), "r"(_parity) : "memory"); \
    } \
} while(0)

#define CP_ASYNC16(smem_u32, gptr) \
    asm volatile("cp.async.cg.shared.global [%0], [%1], 16;" \
        :: "r"((uint32_t)(smem_u32)), "l"(gptr) : "memory")
#define CP_ASYNC_COMMIT() asm volatile("cp.async.commit_group;" ::: "memory")
#define CP_ASYNC_WAIT(n)  asm volatile("cp.async.wait_group %0;" :: "n"(n) : "memory")

#if TC_OK
#define TCGEN05_ALLOC(smem_result_addr, nCols) \
    asm volatile("tcgen05.alloc.cta_group::1.sync.aligned.shared::cta.b32 [%0], %1;" \
        :: "r"((uint32_t)(smem_result_addr)), "r"((uint32_t)(nCols)) : "memory")
#define TCGEN05_DEALLOC(tmem_addr, nCols) \
    asm volatile("tcgen05.dealloc.cta_group::1.sync.aligned.b32 %0, %1;" :: "r"(tmem_addr), "r"((uint32_t)(nCols)))
#define TCGEN05_RELINQUISH() \
    asm volatile("tcgen05.relinquish_alloc_permit.cta_group::1.sync.aligned;")
#define TCGEN05_COMMIT(mbar_smem_addr) \
    asm volatile("tcgen05.commit.cta_group::1.mbarrier::arrive::one.shared::cluster.b64 [%0];" \
        :: "r"((uint32_t)(mbar_smem_addr)) : "memory")
#define TCGEN05_FENCE_AFTER()  asm volatile("tcgen05.fence::after_thread_sync;" ::: "memory")
#define TCGEN05_WAIT_LD()      asm volatile("tcgen05.wait::ld.sync.aligned;" ::: "memory")
#define TCGEN05_LD_32X32B_X32(r, tmem_addr) \
    asm volatile("tcgen05.ld.sync.aligned.32x32b.x32.b32 " \
        "{%0, %1, %2, %3, %4, %5, %6, %7, %8, %9, %10, %11, %12, %13, %14, %15, " \
        "%16, %17, %18, %19, %20, %21, %22, %23, %24, %25, %26, %27, %28, %29, %30, %31}, [%32];" \
        : "=r"((r)[0]),  "=r"((r)[1]),  "=r"((r)[2]),  "=r"((r)[3]), \
          "=r"((r)[4]),  "=r"((r)[5]),  "=r"((r)[6]),  "=r"((r)[7]), \
          "=r"((r)[8]),  "=r"((r)[9]),  "=r"((r)[10]), "=r"((r)[11]), \
          "=r"((r)[12]), "=r"((r)[13]), "=r"((r)[14]), "=r"((r)[15]), \
          "=r"((r)[16]), "=r"((r)[17]), "=r"((r)[18]), "=r"((r)[19]), \
          "=r"((r)[20]), "=r"((r)[21]), "=r"((r)[22]), "=r"((r)[23]), \
          "=r"((r)[24]), "=r"((r)[25]), "=r"((r)[26]), "=r"((r)[27]), \
          "=r"((r)[28]), "=r"((r)[29]), "=r"((r)[30]), "=r"((r)[31]) \
        : "r"(tmem_addr))
__device__ __forceinline__ void mma_f16_ss(uint32_t d, uint64_t a, uint64_t b,
                                           uint32_t idesc, uint32_t en) {
    asm volatile(
        "{\n\t.reg .pred p;\n\tsetp.ne.u32 p, %5, 0;\n\t"
        "tcgen05.mma.cta_group::1.kind::f16 [%0], %1, %2, %3, {%4, %4, %4, %4}, p;\n\t}"
        :: "r"(d), "l"(a), "l"(b), "r"(idesc), "r"(0u), "r"(en) : "memory");
}
#else
#define TCGEN05_ALLOC(a, n)      ((void)0)
#define TCGEN05_DEALLOC(t, n)    ((void)0)
#define TCGEN05_RELINQUISH()     ((void)0)
#define TCGEN05_COMMIT(m)        ((void)0)
#define TCGEN05_FENCE_AFTER()    ((void)0)
#define TCGEN05_WAIT_LD()        ((void)0)
#define TCGEN05_LD_32X32B_X32(r, t) do { _Pragma("unroll") \
    for (int _i = 0; _i < 32; _i++) (r)[_i] = 0u; (void)(t); } while(0)
__device__ __forceinline__ void mma_f16_ss(uint32_t, uint64_t, uint64_t, uint32_t, uint32_t) {}
#endif

#define SMEM_SWIZZLE_128B(off) ((off) ^ (((off) >> 3) & 0x70))
static constexpr uint64_t SMEM_DESC_BASE_SW128 =
    (uint64_t(2) << 61) | (uint64_t(1) << 46) | (uint64_t(64) << 32) | (uint64_t(1) << 16);
#define MAKE_SMEM_DESC(base_addr) (SMEM_DESC_BASE_SW128 | ((uint64_t)((base_addr) >> 4) & 0x3FFF))

// ---------------- x -> bf16 hi/lo split ----------------
__global__ __launch_bounds__(256) void split_kernel(
    const float* __restrict__ src, __nv_bfloat16* __restrict__ hi,
    __nv_bfloat16* __restrict__ lo)
{
    size_t i = ((size_t)blockIdx.x * 256 + threadIdx.x) * 4;
    float4 v = *(const float4*)(src + i);
    __nv_bfloat162 h01 = __floats2bfloat162_rn(v.x, v.y);
    __nv_bfloat162 h23 = __floats2bfloat162_rn(v.z, v.w);
    __nv_bfloat162 l01 = __floats2bfloat162_rn(v.x - __bfloat162float(h01.x),
                                               v.y - __bfloat162float(h01.y));
    __nv_bfloat162 l23 = __floats2bfloat162_rn(v.z - __bfloat162float(h23.x),
                                               v.w - __bfloat162float(h23.y));
    *(uint2*)(hi + i) = make_uint2(*(uint32_t*)&h01, *(uint32_t*)&h23);
    *(uint2*)(lo + i) = make_uint2(*(uint32_t*)&l01, *(uint32_t*)&l23);
}

// ---------------- weight transpose + bf16 hi/lo split: W[K,N] -> T[N,K] ----------------
__global__ __launch_bounds__(256) void wconv_kernel(
    const float* __restrict__ W, __nv_bfloat16* __restrict__ Th,
    __nv_bfloat16* __restrict__ Tl, int K, int N)
{
    __shared__ float t[32][33];
    int n0 = blockIdx.x * 32, k0 = blockIdx.y * 32;
    int tx = threadIdx.x & 31, ty = threadIdx.x >> 5;
    #pragma unroll
    for (int dy = 0; dy < 32; dy += 8)
        t[ty + dy][tx] = W[(size_t)(k0 + ty + dy) * N + n0 + tx];
    __syncthreads();
    #pragma unroll
    for (int dy = 0; dy < 32; dy += 8) {
        float v = t[tx][ty + dy];
        __nv_bfloat16 h = __float2bfloat16(v);
        size_t o = (size_t)(n0 + ty + dy) * K + k0 + tx;
        Th[o] = h;
        Tl[o] = __float2bfloat16(v - __bfloat162float(h));
    }
}

// ---------------- tcgen05 bf16-split GEMM, quarter-unit pipeline ----------------
// Two 96KB SW128 stages, each split into two K=32 half-units (disjoint 16B chunk
// ranges c:{0..3} / {4..7} per 128B row). 4 units of 48KB in flight: fill(u+4)
// waits MMA(u) while MMAs u+1..u+3 have resident data -> tensor runs back-to-back.
#define BM 128
#define BN 256
#define SM_AH 0
#define SM_AL 16384
#define SM_BH 32768
#define SM_BL 65536
#define STAGE_BYTES 98304
#define SM_TILES 1024
#define GEMM_SMEM (SM_TILES + 2 * STAGE_BYTES)   // 197632
#define NU (KDIM / 32)                           // 32 units of K=32

// Fill one half-unit (48KB): A 128 rows + B 256 rows, chunks c = 4h..4h+3.
__device__ __forceinline__ void fill_unit(
    uint32_t sb, uint32_t stBase, int h, int tid,
    const __nv_bfloat16* __restrict__ Ahb, const __nv_bfloat16* __restrict__ Alb,
    const __nv_bfloat16* __restrict__ Bhb, const __nv_bfloat16* __restrict__ Blb)
{
    const int hc = 4 * h;
    #pragma unroll
    for (int l = 0; l < 2; l++) {                 // A: 512 chunks
        int i = tid + l * 256;
        int row = i >> 2, cc = i & 3;
        uint32_t sw = SMEM_SWIZZLE_128B((uint32_t)(row * 128 + (cc + hc) * 16));
        const size_t go = (size_t)row * KDIM + cc * 8;
        CP_ASYNC16(sb + stBase + SM_AH + sw, Ahb + go);
        CP_ASYNC16(sb + stBase + SM_AL + sw, Alb + go);
    }
    #pragma unroll
    for (int l = 0; l < 4; l++) {                 // B: 1024 chunks
        int i = tid + l * 256;
        int row = i >> 2, cc = i & 3;
        uint32_t sw = SMEM_SWIZZLE_128B((uint32_t)(row * 128 + (cc + hc) * 16));
        const size_t go = (size_t)row * KDIM + cc * 8;
        CP_ASYNC16(sb + stBase + SM_BH + sw, Bhb + go);
        CP_ASYNC16(sb + stBase + SM_BL + sw, Blb + go);
    }
}

__global__ __launch_bounds__(256, 1) void tc_gemm(
    const __nv_bfloat16* __restrict__ Ah, const __nv_bfloat16* __restrict__ Al,
    const __nv_bfloat16* __restrict__ Bh, const __nv_bfloat16* __restrict__ Bl,
    const float* __restrict__ bias,
    float* __restrict__ C, int Ntot)
{
    extern __shared__ char smem[];
    const uint32_t sb = smem_to_u32(smem);
    const int tid = threadIdx.x, wid = tid >> 5, lid = tid & 31;
    const int mBase = blockIdx.y * BM;
    const int nBase = blockIdx.x * BN;

    if (tid == 0) {                               // done-barrier per unit slot
        #pragma unroll
        for (int b = 0; b < 4; b++) MBARRIER_INIT(sb + 8 + b * 8, 1);
    }
    if (wid == 0) { TCGEN05_ALLOC(sb + 0, 256); TCGEN05_RELINQUISH(); }
    __syncthreads();
    uint32_t tmem;
    asm volatile("ld.shared.b32 %0, [%1];" : "=r"(tmem) : "r"(sb));

    const uint32_t idesc = (1u << 4) | (1u << 7) | (1u << 10)
                         | ((BN / 8) << 17) | ((BM / 16) << 24);

    const __nv_bfloat16* AhB = Ah + (size_t)mBase * KDIM;
    const __nv_bfloat16* AlB = Al + (size_t)mBase * KDIM;
    const __nv_bfloat16* BhB = Bh + (size_t)nBase * KDIM;
    const __nv_bfloat16* BlB = Bl + (size_t)nBase * KDIM;

    // prologue: fill units 0..3 (fills both stages completely)
    #pragma unroll
    for (int u = 0; u < 4; u++) {
        const uint32_t stBase = SM_TILES + ((u >> 1) & 1) * STAGE_BYTES;
        const int k0 = u * 32;
        fill_unit(sb, stBase, u & 1, tid, AhB + k0, AlB + k0, BhB + k0, BlB + k0);
        CP_ASYNC_COMMIT();
    }

    int ph[4] = {0, 0, 0, 0};
    for (int u = 0; u < NU; u++) {
        const int st = (u >> 1) & 1, h = u & 1, b = u & 3;
        const uint32_t stBase = SM_TILES + st * STAGE_BYTES;

        if (u < NU - 3)      CP_ASYNC_WAIT(3);
        else if (u == NU - 3) CP_ASYNC_WAIT(2);
        else if (u == NU - 2) CP_ASYNC_WAIT(1);
        else                 CP_ASYNC_WAIT(0);
        __syncthreads();

        if (wid == 0 && elect_one_pred()) {
            asm volatile("fence.proxy.async.shared::cta;" ::: "memory");
            uint64_t dAh = MAKE_SMEM_DESC(sb + stBase + SM_AH);
            uint64_t dAl = MAKE_SMEM_DESC(sb + stBase + SM_AL);
            uint64_t dBh = MAKE_SMEM_DESC(sb + stBase + SM_BH);
            uint64_t dBl = MAKE_SMEM_DESC(sb + stBase + SM_BL);
            #pragma unroll
            for (int j = 0; j < 2; j++) {
                const int ks = 2 * h + j;
                uint32_t acc0 = (u == 0 && j == 0) ? 0u : 1u;
                mma_f16_ss(tmem, dAh + ks * 2, dBh + ks * 2, idesc, acc0);
                mma_f16_ss(tmem, dAh + ks * 2, dBl + ks * 2, idesc, 1u);
                mma_f16_ss(tmem, dAl + ks * 2, dBh + ks * 2, idesc, 1u);
            }
            TCGEN05_COMMIT(sb + 8 + b * 8);
        }

        if (u + 4 < NU) {
            MBARRIER_WAIT_PARITY(sb + 8 + b * 8, ph[b]);  // MMAs(u) done -> slot free
            ph[b] ^= 1;
            const int k4 = (u + 4) * 32;
            fill_unit(sb, stBase, h, tid, AhB + k4, AlB + k4, BhB + k4, BlB + k4);
            CP_ASYNC_COMMIT();
        }
    }
    // drain: last 4 commits (units 28..31 on slots 0..3)
    #pragma unroll
    for (int b = 0; b < 4; b++) MBARRIER_WAIT_PARITY(sb + 8 + b * 8, ph[b]);
    TCGEN05_FENCE_AFTER();

    if (wid < 4) {
        int row = mBase + wid * 32 + lid;
        float* crow = C + (size_t)row * Ntot + nBase;
        for (int nb = 0; nb < BN; nb += 32) {
            uint32_t r[32];
            TCGEN05_LD_32X32B_X32(r, tmem + nb);
            TCGEN05_WAIT_LD();
            #pragma unroll
            for (int j = 0; j < 32; j += 4) {
                float4 v;
                v.x = __uint_as_float(r[j + 0]);
                v.y = __uint_as_float(r[j + 1]);
                v.z = __uint_as_float(r[j + 2]);
                v.w = __uint_as_float(r[j + 3]);
                if (bias) {
                    const float* bp = bias + nBase + nb + j;
                    v.x += bp[0]; v.y += bp[1]; v.z += bp[2]; v.w += bp[3];
                }
                *(float4*)(crow + nb + j) = v;
            }
        }
    }
    __syncthreads();
    if (tid == 0) {
        #pragma unroll
        for (int b = 0; b < 4; b++) MBARRIER_INVAL(sb + 8 + b * 8);
    }
    if (wid == 0) { TCGEN05_DEALLOC(tmem, 256); }
}

// ---------------- gate math (identical fp32 formula everywhere) ----------------
__device__ __forceinline__ void gate2(const float* __restrict__ p, int d0,
                                      float bx, float by, float2& a, float2& s)
{
    float2 ap = *(const float2*)(p + d0);
    float2 ip = *(const float2*)(p + DREC + d0);
    float2 vv = *(const float2*)(p + 2 * DREC + d0);
    a.x = 1.f / (1.f + expf(-(ap.x + bx)));
    a.y = 1.f / (1.f + expf(-(ap.y + by)));
    s.x = sqrtf(fmaxf(1.f - a.x * a.x, 1e-8f)) * (vv.x / (1.f + expf(-ip.x)));
    s.y = sqrtf(fmaxf(1.f - a.y * a.y, 1e-8f)) * (vv.y / (1.f + expf(-ip.y)));
}

// ---------------- phase 1: per-chunk stats, act fused ----------------
__global__ __launch_bounds__(256) void chunk_stats_kernel(const float* __restrict__ db)
{
    int d0 = (blockIdx.x * 256 + threadIdx.x) * 2;
    int c  = blockIdx.y;
    int b  = blockIdx.z;
    size_t rowBase = (size_t)b * SEQ + (size_t)c * CHUNKSZ;
    float bx = db[d0], by = db[d0 + 1];

    float cl0 = 0.f, cd0 = 1.f, ws0 = 0.f;
    float cl1 = 0.f, cd1 = 1.f, ws1 = 0.f;
    #pragma unroll 4
    for (int j = 0; j < CHUNKSZ; j++) {
        const float* p = g_aiv + (rowBase + j) * (3 * DREC);
        float2 a, s;
        gate2(p, d0, bx, by, a, s);
        cl0 += logf(fmaxf(a.x, 1e-10f));  cd0 = expf(cl0);
        cl1 += logf(fmaxf(a.y, 1e-10f));  cd1 = expf(cl1);
        ws0 += s.x / fmaxf(cd0, 1e-10f);
        ws1 += s.y / fmaxf(cd1, 1e-10f);
    }
    int o = (b * NCHUNK + c) * DREC + d0;
    *(float2*)(g_ctd + o) = make_float2(cd0, cd1);
    *(float2*)(g_cfs + o) = make_float2(cd0 * ws0, cd1 * ws1);
}

// ---------------- phase 2: serial inter-chunk scan (register-prefetched) ----------------
__global__ __launch_bounds__(256) void interchunk_kernel()
{
    int d = blockIdx.x * 256 + threadIdx.x;
    int b = blockIdx.y;
    float cl = 0.f, ccd = 1.f, cw = 0.f;
    for (int cb = 0; cb < NCHUNK; cb += 8) {
        float td[8], fs[8];
        #pragma unroll
        for (int u = 0; u < 8; u++) {
            int o = (b * NCHUNK + cb + u) * DREC + d;
            td[u] = g_ctd[o];
            fs[u] = g_cfs[o];
        }
        #pragma unroll
        for (int u = 0; u < 8; u++) {
            int o = (b * NCHUNK + cb + u) * DREC + d;
            g_inc[o] = ccd * cw;
            cl += logf(fmaxf(td[u], 1e-10f));
            ccd = expf(cl);
            cw += fs[u] / fmaxf(ccd, 1e-10f);
        }
    }
}

// ---------------- phase 3: final states, act fused -> h hi/lo bf16 ----------------
__global__ __launch_bounds__(256) void states_kernel(const float* __restrict__ db)
{
    int d0 = (blockIdx.x * 256 + threadIdx.x) * 2;
    int c  = blockIdx.y;
    int b  = blockIdx.z;
    size_t rowBase = (size_t)b * SEQ + (size_t)c * CHUNKSZ;
    float bx = db[d0], by = db[d0 + 1];
    const float2 inc = *(const float2*)(g_inc + (b * NCHUNK + c) * DREC + d0);

    float cl0 = 0.f, ws0 = 0.f, cl1 = 0.f, ws1 = 0.f;
    #pragma unroll 4
    for (int j = 0; j < CHUNKSZ; j++) {
        const float* p = g_aiv + (rowBase + j) * (3 * DREC);
        float2 a, s;
        gate2(p, d0, bx, by, a, s);
        cl0 += logf(fmaxf(a.x, 1e-10f));
        cl1 += logf(fmaxf(a.y, 1e-10f));
        float cd0 = expf(cl0), cd1 = expf(cl1);
        ws0 += s.x / fmaxf(cd0, 1e-10f);
        ws1 += s.y / fmaxf(cd1, 1e-10f);
        float h0 = cd0 * ws0 + cd0 * inc.x;
        float h1 = cd1 * ws1 + cd1 * inc.y;
        __nv_bfloat162 hh = __floats2bfloat162_rn(h0, h1);
        __nv_bfloat162 hl = __floats2bfloat162_rn(h0 - __bfloat162float(hh.x),
                                                  h1 - __bfloat162float(hh.y));
        size_t idx = (rowBase + j) * DREC + d0;
        *(uint32_t*)(g_hh + idx) = *(uint32_t*)&hh;
        *(uint32_t*)(g_hl + idx) = *(uint32_t*)&hl;
    }
}

// ---------------- launcher ----------------
extern "C" void kernel_launch(void* const* d_in, const int* in_sizes, int n_in,
                              void* d_out, int out_size)
{
    const float* x          = (const float*)d_in[0];
    const float* W_aiv      = (const float*)d_in[1];
    const float* decay_bias = (const float*)d_in[2];
    const float* W_mix      = (const float*)d_in[3];
    const float* b_mix      = (const float*)d_in[4];
    float*       out        = (float*)d_out;

    float* aiv_p;
    __nv_bfloat16 *xh, *xl, *hh, *hl, *w1th, *w1tl, *w2th, *w2tl;
    cudaGetSymbolAddress((void**)&aiv_p, g_aiv);
    cudaGetSymbolAddress((void**)&xh,    g_xh);
    cudaGetSymbolAddress((void**)&xl,    g_xl);
    cudaGetSymbolAddress((void**)&hh,    g_hh);
    cudaGetSymbolAddress((void**)&hl,    g_hl);
    cudaGetSymbolAddress((void**)&w1th,  g_w1th);
    cudaGetSymbolAddress((void**)&w1tl,  g_w1tl);
    cudaGetSymbolAddress((void**)&w2th,  g_w2th);
    cudaGetSymbolAddress((void**)&w2tl,  g_w2tl);

    cudaFuncSetAttribute(tc_gemm, cudaFuncAttributeMaxDynamicSharedMemorySize, GEMM_SMEM);

    split_kernel<<<(MROWS * KDIM) / 1024, 256>>>(x, xh, xl);
    wconv_kernel<<<dim3(3072 / 32, 1024 / 32), 256>>>(W_aiv, w1th, w1tl, 1024, 3072);
    wconv_kernel<<<dim3(1024 / 32, 1024 / 32), 256>>>(W_mix, w2th, w2tl, 1024, 1024);

    // 1) aiv = x @ W_aiv
    tc_gemm<<<dim3(3072 / BN, MROWS / BM), 256, GEMM_SMEM>>>(xh, xl, w1th, w1tl, nullptr, aiv_p, 3072);
    // 2+3) chunked scan with act fused
    chunk_stats_kernel<<<dim3(DREC / 512, NCHUNK, BATCH), 256>>>(decay_bias);
    interchunk_kernel<<<dim3(DREC / 256, BATCH), 256>>>();
    states_kernel<<<dim3(DREC / 512, NCHUNK, BATCH), 256>>>(decay_bias);
    // 4) out = h @ W_mix + b_mix
    tc_gemm<<<dim3(1024 / BN, MROWS / BM), 256, GEMM_SMEM>>>(hh, hl, w2th, w2tl, b_mix, out, 1024);
}

// round 12
// speedup vs baseline: 1.3722x; 1.3722x over previous
#include <cuda_runtime.h>
#include <cuda_bf16.h>
#include <math.h>
#include <cstdint>

#define SEQ     8192
#define BATCH   4
#define DREC    1024
#define NCHUNK  128
#define CHUNKSZ 64
#define MROWS   (BATCH * SEQ)      // 32768
#define KDIM    1024

#if defined(__CUDA_ARCH_FEAT_SM103_ALL) || defined(__CUDA_ARCH_FEAT_SM100_ALL) || defined(__CUDA_ARCH_FEAT_SM101_ALL)
#define TC_OK 1
#else
#define TC_OK 0
#endif

// ---------------- scratch ----------------
__device__ float g_aiv[(size_t)MROWS * 3 * DREC];
__device__ float g_ctd[BATCH * NCHUNK * DREC];
__device__ float g_cfs[BATCH * NCHUNK * DREC];
__device__ float g_inc[BATCH * NCHUNK * DREC];
__device__ __nv_bfloat16 g_xh[(size_t)MROWS * KDIM];
__device__ __nv_bfloat16 g_xl[(size_t)MROWS * KDIM];
__device__ __nv_bfloat16 g_hh[(size_t)MROWS * DREC];
__device__ __nv_bfloat16 g_hl[(size_t)MROWS * DREC];
__device__ __nv_bfloat16 g_w1th[3072 * 1024];
__device__ __nv_bfloat16 g_w1tl[3072 * 1024];
__device__ __nv_bfloat16 g_w2th[1024 * 1024];
__device__ __nv_bfloat16 g_w2tl[1024 * 1024];

// ---------------- PTX helpers ----------------
__device__ __forceinline__ uint32_t smem_to_u32(const void* p) {
    uint32_t a;
    asm("{ .reg .u64 t; cvta.to.shared.u64 t, %1; cvt.u32.u64 %0, t; }" : "=r"(a) : "l"(p));
    return a;
}
__device__ __forceinline__ uint32_t elect_one_pred() {
    uint32_t p;
    asm volatile("{\n\t.reg .pred p;\n\telect.sync _|p, 0xFFFFFFFF;\n\tselp.b32 %0, 1, 0, p;\n\t}" : "=r"(p));
    return p;
}
#define MBARRIER_INIT(addr, cnt) \
    asm volatile("mbarrier.init.shared.b64 [%0], %1;" :: "r"((uint32_t)(addr)), "r"((uint32_t)(cnt)) : "memory")
#define MBARRIER_INVAL(addr) \
    asm volatile("mbarrier.inval.shared.b64 [%0];" :: "r"((uint32_t)(addr)) : "memory")
#define MBARRIER_WAIT_PARITY(mbar_smem_addr, phase_parity) do { \
    uint32_t _mbar = (uint32_t)(mbar_smem_addr); \
    uint32_t _parity = (uint32_t)(phase_parity); \
    uint32_t _done; \
    asm volatile("{\n\t.reg .pred p;\n\t" \
        "mbarrier.try_wait.parity.acquire.cta.shared::cta.b64 p, [%1], %2;\n\t" \
        "selp.b32 %0, 1, 0, p;\n\t}" \
        : "=r"(_done) : "r"(_mbar), "r"(_parity) : "memory"); \
    if (!_done) { \
        asm volatile("{\n\t.reg .pred P1;\n\t" \
            "WAIT_LOOP_%=:\n\t" \
            "mbarrier.try_wait.parity.acquire.cta.shared::cta.b64 P1, [%0], %1, 0x989680;\n\t" \
            "@P1 bra.uni WAIT_DONE_%=;\n\t" \
            "bra.uni WAIT_LOOP_%=;\n\t" \
            "WAIT_DONE_%=:\n\t}" \
            :: "r"(_mbar), "r"(_parity) : "memory"); \
    } \
} while(0)

#define CP_ASYNC16(smem_u32, gptr) \
    asm volatile("cp.async.cg.shared.global [%0], [%1], 16;" \
        :: "r"((uint32_t)(smem_u32)), "l"(gptr) : "memory")
// .noinc: this thread contributes exactly ONE net arrival (fires when all its
// prior cp.asyncs complete). Without .noinc the pending count is pre-incremented
// and the arrive nets to zero -> barrier never flips (R11 deadlock).
#define CP_ASYNC_MB_ARRIVE_NOINC(addr) \
    asm volatile("cp.async.mbarrier.arrive.noinc.shared.b64 [%0];" \
        :: "r"((uint32_t)(addr)) : "memory")

#if TC_OK
#define TCGEN05_ALLOC(smem_result_addr, nCols) \
    asm volatile("tcgen05.alloc.cta_group::1.sync.aligned.shared::cta.b32 [%0], %1;" \
        :: "r"((uint32_t)(smem_result_addr)), "r"((uint32_t)(nCols)) : "memory")
#define TCGEN05_DEALLOC(tmem_addr, nCols) \
    asm volatile("tcgen05.dealloc.cta_group::1.sync.aligned.b32 %0, %1;" :: "r"(tmem_addr), "r"((uint32_t)(nCols)))
#define TCGEN05_RELINQUISH() \
    asm volatile("tcgen05.relinquish_alloc_permit.cta_group::1.sync.aligned;")
#define TCGEN05_COMMIT(mbar_smem_addr) \
    asm volatile("tcgen05.commit.cta_group::1.mbarrier::arrive::one.shared::cluster.b64 [%0];" \
        :: "r"((uint32_t)(mbar_smem_addr)) : "memory")
#define TCGEN05_FENCE_AFTER()  asm volatile("tcgen05.fence::after_thread_sync;" ::: "memory")
#define TCGEN05_WAIT_LD()      asm volatile("tcgen05.wait::ld.sync.aligned;" ::: "memory")
#define TCGEN05_LD_32X32B_X32(r, tmem_addr) \
    asm volatile("tcgen05.ld.sync.aligned.32x32b.x32.b32 " \
        "{%0, %1, %2, %3, %4, %5, %6, %7, %8, %9, %10, %11, %12, %13, %14, %15, " \
        "%16, %17, %18, %19, %20, %21, %22, %23, %24, %25, %26, %27, %28, %29, %30, %31}, [%32];" \
        : "=r"((r)[0]),  "=r"((r)[1]),  "=r"((r)[2]),  "=r"((r)[3]), \
          "=r"((r)[4]),  "=r"((r)[5]),  "=r"((r)[6]),  "=r"((r)[7]), \
          "=r"((r)[8]),  "=r"((r)[9]),  "=r"((r)[10]), "=r"((r)[11]), \
          "=r"((r)[12]), "=r"((r)[13]), "=r"((r)[14]), "=r"((r)[15]), \
          "=r"((r)[16]), "=r"((r)[17]), "=r"((r)[18]), "=r"((r)[19]), \
          "=r"((r)[20]), "=r"((r)[21]), "=r"((r)[22]), "=r"((r)[23]), \
          "=r"((r)[24]), "=r"((r)[25]), "=r"((r)[26]), "=r"((r)[27]), \
          "=r"((r)[28]), "=r"((r)[29]), "=r"((r)[30]), "=r"((r)[31]) \
        : "r"(tmem_addr))
__device__ __forceinline__ void mma_f16_ss(uint32_t d, uint64_t a, uint64_t b,
                                           uint32_t idesc, uint32_t en) {
    asm volatile(
        "{\n\t.reg .pred p;\n\tsetp.ne.u32 p, %5, 0;\n\t"
        "tcgen05.mma.cta_group::1.kind::f16 [%0], %1, %2, %3, {%4, %4, %4, %4}, p;\n\t}"
        :: "r"(d), "l"(a), "l"(b), "r"(idesc), "r"(0u), "r"(en) : "memory");
}
#else
#define TCGEN05_ALLOC(a, n)      ((void)0)
#define TCGEN05_DEALLOC(t, n)    ((void)0)
#define TCGEN05_RELINQUISH()     ((void)0)
#define TCGEN05_COMMIT(m)        ((void)0)
#define TCGEN05_FENCE_AFTER()    ((void)0)
#define TCGEN05_WAIT_LD()        ((void)0)
#define TCGEN05_LD_32X32B_X32(r, t) do { _Pragma("unroll") \
    for (int _i = 0; _i < 32; _i++) (r)[_i] = 0u; (void)(t); } while(0)
__device__ __forceinline__ void mma_f16_ss(uint32_t, uint64_t, uint64_t, uint32_t, uint32_t) {}
#endif

#define SMEM_SWIZZLE_128B(off) ((off) ^ (((off) >> 3) & 0x70))
static constexpr uint64_t SMEM_DESC_BASE_SW128 =
    (uint64_t(2) << 61) | (uint64_t(1) << 46) | (uint64_t(64) << 32) | (uint64_t(1) << 16);
#define MAKE_SMEM_DESC(base_addr) (SMEM_DESC_BASE_SW128 | ((uint64_t)((base_addr) >> 4) & 0x3FFF))

// ---------------- x -> bf16 hi/lo split ----------------
__global__ __launch_bounds__(256) void split_kernel(
    const float* __restrict__ src, __nv_bfloat16* __restrict__ hi,
    __nv_bfloat16* __restrict__ lo)
{
    size_t i = ((size_t)blockIdx.x * 256 + threadIdx.x) * 4;
    float4 v = *(const float4*)(src + i);
    __nv_bfloat162 h01 = __floats2bfloat162_rn(v.x, v.y);
    __nv_bfloat162 h23 = __floats2bfloat162_rn(v.z, v.w);
    __nv_bfloat162 l01 = __floats2bfloat162_rn(v.x - __bfloat162float(h01.x),
                                               v.y - __bfloat162float(h01.y));
    __nv_bfloat162 l23 = __floats2bfloat162_rn(v.z - __bfloat162float(h23.x),
                                               v.w - __bfloat162float(h23.y));
    *(uint2*)(hi + i) = make_uint2(*(uint32_t*)&h01, *(uint32_t*)&h23);
    *(uint2*)(lo + i) = make_uint2(*(uint32_t*)&l01, *(uint32_t*)&l23);
}

// ---------------- weight transpose + bf16 hi/lo split: W[K,N] -> T[N,K] ----------------
__global__ __launch_bounds__(256) void wconv_kernel(
    const float* __restrict__ W, __nv_bfloat16* __restrict__ Th,
    __nv_bfloat16* __restrict__ Tl, int K, int N)
{
    __shared__ float t[32][33];
    int n0 = blockIdx.x * 32, k0 = blockIdx.y * 32;
    int tx = threadIdx.x & 31, ty = threadIdx.x >> 5;
    #pragma unroll
    for (int dy = 0; dy < 32; dy += 8)
        t[ty + dy][tx] = W[(size_t)(k0 + ty + dy) * N + n0 + tx];
    __syncthreads();
    #pragma unroll
    for (int dy = 0; dy < 32; dy += 8) {
        float v = t[tx][ty + dy];
        __nv_bfloat16 h = __float2bfloat16(v);
        size_t o = (size_t)(n0 + ty + dy) * K + k0 + tx;
        Th[o] = h;
        Tl[o] = __float2bfloat16(v - __bfloat162float(h));
    }
}

// ---------------- tcgen05 bf16-split GEMM, warp-specialized 2-stage pipeline ----------
// Warp 0: MMA-only (wait full(st) -> 12 MMAs -> commit done(st)).
// Warps 1-7 (224 threads): producers (wait done(st) -> cp.async refill ->
// cp.async.mbarrier.arrive.noinc on full(st)). No CTA-wide sync in the mainloop.
#define BM 128
#define BN 256
#define KC 64
#define SM_AH 0
#define SM_AL 16384
#define SM_BH 32768
#define SM_BL 65536
#define STAGE_BYTES 98304
#define SM_TILES 1024
#define GEMM_SMEM (SM_TILES + 2 * STAGE_BYTES)   // 197632
#define NKI (KDIM / KC)                          // 16
#define NPROD 224
// ctrl: [0] tmem ptr; full0 @8, full1 @16 (count 224); done0 @24, done1 @32 (count 1)

__device__ __forceinline__ void fill_stage(
    uint32_t sb, uint32_t stBase, int pt,
    const __nv_bfloat16* __restrict__ Ahb, const __nv_bfloat16* __restrict__ Alb,
    const __nv_bfloat16* __restrict__ Bhb, const __nv_bfloat16* __restrict__ Blb)
{
    for (int i = pt; i < 1024; i += NPROD) {      // A: 128 rows x 8 chunks, hi+lo
        int row = i >> 3, c = i & 7;
        uint32_t sw = SMEM_SWIZZLE_128B((uint32_t)(row * 128 + c * 16));
        const size_t go = (size_t)row * KDIM + c * 8;
        CP_ASYNC16(sb + stBase + SM_AH + sw, Ahb + go);
        CP_ASYNC16(sb + stBase + SM_AL + sw, Alb + go);
    }
    for (int i = pt; i < 2048; i += NPROD) {      // B: 256 rows x 8 chunks, hi+lo
        int row = i >> 3, c = i & 7;
        uint32_t sw = SMEM_SWIZZLE_128B((uint32_t)(row * 128 + c * 16));
        const size_t go = (size_t)row * KDIM + c * 8;
        CP_ASYNC16(sb + stBase + SM_BH + sw, Bhb + go);
        CP_ASYNC16(sb + stBase + SM_BL + sw, Blb + go);
    }
}

__global__ __launch_bounds__(256, 1) void tc_gemm(
    const __nv_bfloat16* __restrict__ Ah, const __nv_bfloat16* __restrict__ Al,
    const __nv_bfloat16* __restrict__ Bh, const __nv_bfloat16* __restrict__ Bl,
    const float* __restrict__ bias,
    float* __restrict__ C, int Ntot)
{
    extern __shared__ char smem[];
    const uint32_t sb = smem_to_u32(smem);
    const int tid = threadIdx.x, wid = tid >> 5, lid = tid & 31;
    const int mBase = blockIdx.y * BM;
    const int nBase = blockIdx.x * BN;

    if (tid == 0) {
        MBARRIER_INIT(sb + 8,  NPROD);   // full0: 224 noinc arrivals
        MBARRIER_INIT(sb + 16, NPROD);   // full1
        MBARRIER_INIT(sb + 24, 1);       // done0: one tcgen05 commit
        MBARRIER_INIT(sb + 32, 1);       // done1
    }
    if (wid == 0) { TCGEN05_ALLOC(sb + 0, 256); TCGEN05_RELINQUISH(); }
    __syncthreads();
    uint32_t tmem;
    asm volatile("ld.shared.b32 %0, [%1];" : "=r"(tmem) : "r"(sb));

    const uint32_t idesc = (1u << 4) | (1u << 7) | (1u << 10)
                         | ((BN / 8) << 17) | ((BM / 16) << 24);

    const __nv_bfloat16* AhB = Ah + (size_t)mBase * KDIM;
    const __nv_bfloat16* AlB = Al + (size_t)mBase * KDIM;
    const __nv_bfloat16* BhB = Bh + (size_t)nBase * KDIM;
    const __nv_bfloat16* BlB = Bl + (size_t)nBase * KDIM;

    if (wid == 0) {
        // ---- MMA warp ----
        if (elect_one_pred()) {
            int fph0 = 0, fph1 = 0;
            for (int kt = 0; kt < NKI; kt++) {
                const int st = kt & 1;
                const uint32_t stBase = SM_TILES + st * STAGE_BYTES;
                if (st == 0) { MBARRIER_WAIT_PARITY(sb + 8,  fph0); fph0 ^= 1; }
                else         { MBARRIER_WAIT_PARITY(sb + 16, fph1); fph1 ^= 1; }
                asm volatile("fence.proxy.async.shared::cta;" ::: "memory");
                uint64_t dAh = MAKE_SMEM_DESC(sb + stBase + SM_AH);
                uint64_t dAl = MAKE_SMEM_DESC(sb + stBase + SM_AL);
                uint64_t dBh = MAKE_SMEM_DESC(sb + stBase + SM_BH);
                uint64_t dBl = MAKE_SMEM_DESC(sb + stBase + SM_BL);
                #pragma unroll
                for (int ks = 0; ks < 4; ks++) {
                    uint32_t acc0 = (kt == 0 && ks == 0) ? 0u : 1u;
                    mma_f16_ss(tmem, dAh + ks * 2, dBh + ks * 2, idesc, acc0);
                    mma_f16_ss(tmem, dAh + ks * 2, dBl + ks * 2, idesc, 1u);
                    mma_f16_ss(tmem, dAl + ks * 2, dBh + ks * 2, idesc, 1u);
                }
                TCGEN05_COMMIT(sb + 24 + st * 8);
            }
        }
    } else {
        // ---- producer warps ----
        const int pt = tid - 32;   // 0..223
        fill_stage(sb, SM_TILES, pt, AhB, AlB, BhB, BlB);
        CP_ASYNC_MB_ARRIVE_NOINC(sb + 8);
        fill_stage(sb, SM_TILES + STAGE_BYTES, pt, AhB + KC, AlB + KC, BhB + KC, BlB + KC);
        CP_ASYNC_MB_ARRIVE_NOINC(sb + 16);

        int dph0 = 0, dph1 = 0;
        for (int kt = 0; kt + 2 < NKI; kt++) {
            const int st = kt & 1;
            const uint32_t stBase = SM_TILES + st * STAGE_BYTES;
            if (st == 0) { MBARRIER_WAIT_PARITY(sb + 24, dph0); dph0 ^= 1; }
            else         { MBARRIER_WAIT_PARITY(sb + 32, dph1); dph1 ^= 1; }
            const int k2 = (kt + 2) * KC;
            fill_stage(sb, stBase, pt, AhB + k2, AlB + k2, BhB + k2, BlB + k2);
            CP_ASYNC_MB_ARRIVE_NOINC(sb + 8 + st * 8);
        }
    }

    // final waits: done0/done1 each flip 8 times total; producers consumed 7,
    // so everyone waits the 8th flip at parity 1. (NKI == 16)
    MBARRIER_WAIT_PARITY(sb + 24, 1);
    MBARRIER_WAIT_PARITY(sb + 32, 1);
    TCGEN05_FENCE_AFTER();

    if (wid < 4) {
        int row = mBase + wid * 32 + lid;
        float* crow = C + (size_t)row * Ntot + nBase;
        for (int nb = 0; nb < BN; nb += 32) {
            uint32_t r[32];
            TCGEN05_LD_32X32B_X32(r, tmem + nb);
            TCGEN05_WAIT_LD();
            #pragma unroll
            for (int j = 0; j < 32; j += 4) {
                float4 v;
                v.x = __uint_as_float(r[j + 0]);
                v.y = __uint_as_float(r[j + 1]);
                v.z = __uint_as_float(r[j + 2]);
                v.w = __uint_as_float(r[j + 3]);
                if (bias) {
                    const float* bp = bias + nBase + nb + j;
                    v.x += bp[0]; v.y += bp[1]; v.z += bp[2]; v.w += bp[3];
                }
                *(float4*)(crow + nb + j) = v;
            }
        }
    }
    __syncthreads();
    if (tid == 0) {
        MBARRIER_INVAL(sb + 8);  MBARRIER_INVAL(sb + 16);
        MBARRIER_INVAL(sb + 24); MBARRIER_INVAL(sb + 32);
    }
    if (wid == 0) { TCGEN05_DEALLOC(tmem, 256); }
}

// ---------------- gate math (identical fp32 formula everywhere) ----------------
__device__ __forceinline__ void gate2(const float* __restrict__ p, int d0,
                                      float bx, float by, float2& a, float2& s)
{
    float2 ap = *(const float2*)(p + d0);
    float2 ip = *(const float2*)(p + DREC + d0);
    float2 vv = *(const float2*)(p + 2 * DREC + d0);
    a.x = 1.f / (1.f + expf(-(ap.x + bx)));
    a.y = 1.f / (1.f + expf(-(ap.y + by)));
    s.x = sqrtf(fmaxf(1.f - a.x * a.x, 1e-8f)) * (vv.x / (1.f + expf(-ip.x)));
    s.y = sqrtf(fmaxf(1.f - a.y * a.y, 1e-8f)) * (vv.y / (1.f + expf(-ip.y)));
}

// ---------------- phase 1: per-chunk stats, act fused ----------------
__global__ __launch_bounds__(256) void chunk_stats_kernel(const float* __restrict__ db)
{
    int d0 = (blockIdx.x * 256 + threadIdx.x) * 2;
    int c  = blockIdx.y;
    int b  = blockIdx.z;
    size_t rowBase = (size_t)b * SEQ + (size_t)c * CHUNKSZ;
    float bx = db[d0], by = db[d0 + 1];

    float cl0 = 0.f, cd0 = 1.f, ws0 = 0.f;
    float cl1 = 0.f, cd1 = 1.f, ws1 = 0.f;
    #pragma unroll 4
    for (int j = 0; j < CHUNKSZ; j++) {
        const float* p = g_aiv + (rowBase + j) * (3 * DREC);
        float2 a, s;
        gate2(p, d0, bx, by, a, s);
        cl0 += logf(fmaxf(a.x, 1e-10f));  cd0 = expf(cl0);
        cl1 += logf(fmaxf(a.y, 1e-10f));  cd1 = expf(cl1);
        ws0 += s.x / fmaxf(cd0, 1e-10f);
        ws1 += s.y / fmaxf(cd1, 1e-10f);
    }
    int o = (b * NCHUNK + c) * DREC + d0;
    *(float2*)(g_ctd + o) = make_float2(cd0, cd1);
    *(float2*)(g_cfs + o) = make_float2(cd0 * ws0, cd1 * ws1);
}

// ---------------- phase 2: serial inter-chunk scan (register-prefetched) ----------------
__global__ __launch_bounds__(256) void interchunk_kernel()
{
    int d = blockIdx.x * 256 + threadIdx.x;
    int b = blockIdx.y;
    float cl = 0.f, ccd = 1.f, cw = 0.f;
    for (int cb = 0; cb < NCHUNK; cb += 8) {
        float td[8], fs[8];
        #pragma unroll
        for (int u = 0; u < 8; u++) {
            int o = (b * NCHUNK + cb + u) * DREC + d;
            td[u] = g_ctd[o];
            fs[u] = g_cfs[o];
        }
        #pragma unroll
        for (int u = 0; u < 8; u++) {
            int o = (b * NCHUNK + cb + u) * DREC + d;
            g_inc[o] = ccd * cw;
            cl += logf(fmaxf(td[u], 1e-10f));
            ccd = expf(cl);
            cw += fs[u] / fmaxf(ccd, 1e-10f);
        }
    }
}

// ---------------- phase 3: final states, act fused -> h hi/lo bf16 ----------------
__global__ __launch_bounds__(256) void states_kernel(const float* __restrict__ db)
{
    int d0 = (blockIdx.x * 256 + threadIdx.x) * 2;
    int c  = blockIdx.y;
    int b  = blockIdx.z;
    size_t rowBase = (size_t)b * SEQ + (size_t)c * CHUNKSZ;
    float bx = db[d0], by = db[d0 + 1];
    const float2 inc = *(const float2*)(g_inc + (b * NCHUNK + c) * DREC + d0);

    float cl0 = 0.f, ws0 = 0.f, cl1 = 0.f, ws1 = 0.f;
    #pragma unroll 4
    for (int j = 0; j < CHUNKSZ; j++) {
        const float* p = g_aiv + (rowBase + j) * (3 * DREC);
        float2 a, s;
        gate2(p, d0, bx, by, a, s);
        cl0 += logf(fmaxf(a.x, 1e-10f));
        cl1 += logf(fmaxf(a.y, 1e-10f));
        float cd0 = expf(cl0), cd1 = expf(cl1);
        ws0 += s.x / fmaxf(cd0, 1e-10f);
        ws1 += s.y / fmaxf(cd1, 1e-10f);
        float h0 = cd0 * ws0 + cd0 * inc.x;
        float h1 = cd1 * ws1 + cd1 * inc.y;
        __nv_bfloat162 hh = __floats2bfloat162_rn(h0, h1);
        __nv_bfloat162 hl = __floats2bfloat162_rn(h0 - __bfloat162float(hh.x),
                                                  h1 - __bfloat162float(hh.y));
        size_t idx = (rowBase + j) * DREC + d0;
        *(uint32_t*)(g_hh + idx) = *(uint32_t*)&hh;
        *(uint32_t*)(g_hl + idx) = *(uint32_t*)&hl;
    }
}

// ---------------- launcher ----------------
extern "C" void kernel_launch(void* const* d_in, const int* in_sizes, int n_in,
                              void* d_out, int out_size)
{
    const float* x          = (const float*)d_in[0];
    const float* W_aiv      = (const float*)d_in[1];
    const float* decay_bias = (const float*)d_in[2];
    const float* W_mix      = (const float*)d_in[3];
    const float* b_mix      = (const float*)d_in[4];
    float*       out        = (float*)d_out;

    float* aiv_p;
    __nv_bfloat16 *xh, *xl, *hh, *hl, *w1th, *w1tl, *w2th, *w2tl;
    cudaGetSymbolAddress((void**)&aiv_p, g_aiv);
    cudaGetSymbolAddress((void**)&xh,    g_xh);
    cudaGetSymbolAddress((void**)&xl,    g_xl);
    cudaGetSymbolAddress((void**)&hh,    g_hh);
    cudaGetSymbolAddress((void**)&hl,    g_hl);
    cudaGetSymbolAddress((void**)&w1th,  g_w1th);
    cudaGetSymbolAddress((void**)&w1tl,  g_w1tl);
    cudaGetSymbolAddress((void**)&w2th,  g_w2th);
    cudaGetSymbolAddress((void**)&w2tl,  g_w2tl);

    cudaFuncSetAttribute(tc_gemm, cudaFuncAttributeMaxDynamicSharedMemorySize, GEMM_SMEM);

    split_kernel<<<(MROWS * KDIM) / 1024, 256>>>(x, xh, xl);
    wconv_kernel<<<dim3(3072 / 32, 1024 / 32), 256>>>(W_aiv, w1th, w1tl, 1024, 3072);
    wconv_kernel<<<dim3(1024 / 32, 1024 / 32), 256>>>(W_mix, w2th, w2tl, 1024, 1024);

    // 1) aiv = x @ W_aiv
    tc_gemm<<<dim3(3072 / BN, MROWS / BM), 256, GEMM_SMEM>>>(xh, xl, w1th, w1tl, nullptr, aiv_p, 3072);
    // 2+3) chunked scan with act fused
    chunk_stats_kernel<<<dim3(DREC / 512, NCHUNK, BATCH), 256>>>(decay_bias);
    interchunk_kernel<<<dim3(DREC / 256, BATCH), 256>>>();
    states_kernel<<<dim3(DREC / 512, NCHUNK, BATCH), 256>>>(decay_bias);
    // 4) out = h @ W_mix + b_mix
    tc_gemm<<<dim3(1024 / BN, MROWS / BM), 256, GEMM_SMEM>>>(hh, hl, w2th, w2tl, b_mix, out, 1024);
}